// round 4
// baseline (speedup 1.0000x reference)
#include <cuda_runtime.h>

// TrigoLinear: out[b,o] = sum_i sin(x[b,i]*w_sin[o,i] + b_sin[o,i]) * w_out[o,i] + b_out[o]
// Hybrid MUFU + packed-f32x2 Taylor-5. Tile 64x64, 512 threads, grid 128, 16 warps/SM.

#define B_DIM   1024
#define IN_DIM  512
#define OUT_DIM 512

#define BM 64
#define BN 64
#define BK 32
#define PADX 66   // x row stride (floats): 2-way STS conflict, float2-aligned loads
#define PADO 68   // o-side row stride: float4-aligned loads (conflict-free within row)

typedef unsigned long long ull;

__device__ __forceinline__ ull pk2(float lo, float hi) {
    ull d; asm("mov.b64 %0, {%1, %2};" : "=l"(d) : "f"(lo), "f"(hi)); return d;
}
__device__ __forceinline__ void upk2(ull d, float& lo, float& hi) {
    asm("mov.b64 {%0, %1}, %2;" : "=f"(lo), "=f"(hi) : "l"(d));
}
__device__ __forceinline__ ull fma2_(ull a, ull b, ull c) {
    ull d; asm("fma.rn.f32x2 %0, %1, %2, %3;" : "=l"(d) : "l"(a), "l"(b), "l"(c)); return d;
}
__device__ __forceinline__ ull mul2_(ull a, ull b) {
    ull d; asm("mul.rn.f32x2 %0, %1, %2;" : "=l"(d) : "l"(a), "l"(b)); return d;
}
__device__ __forceinline__ float sin_mufu(float a) {
    float d; asm("sin.approx.f32 %0, %1;" : "=f"(d) : "f"(a)); return d;
}

__global__ __launch_bounds__(512, 1)
void trigo_kernel(const float* __restrict__ x,
                  const float* __restrict__ weight,
                  const float* __restrict__ bias,
                  float* __restrict__ out) {
    __shared__ __align__(16) float sx [BK * PADX];  // [k][b]
    __shared__ __align__(16) float sws[BK * PADO];  // [k][o] w_sin
    __shared__ __align__(16) float sbs[BK * PADO];  // [k][o] b_sin
    __shared__ __align__(16) float swo[BK * PADO];  // [k][o] w_out

    const int tid = threadIdx.x;
    const int tx = tid & 15;   // 4 outs/thread: o = tx*4
    const int ty = tid >> 4;   // 2 rows/thread: b = ty*2  (ty 0..31)
    const int bRow = blockIdx.y * BM;
    const int oCol = blockIdx.x * BN;

    const float2* __restrict__ w2 = (const float2*)weight;

    // register staging (4 per stream per thread at 512 threads)
    float  rx[4];
    float2 rw[4];
    float  rb[4];

    // ---- prologue: tile 0 ----
    #pragma unroll
    for (int j = 0; j < 4; j++) {
        int idx = tid + j * 512;
        int r = idx >> 5, k = idx & 31;
        rx[j] = x[(bRow + r) * IN_DIM + k];
        rw[j] = w2[(oCol + r) * IN_DIM + k];
        rb[j] = bias[(oCol + r) * (IN_DIM + 1) + k];
    }
    #pragma unroll
    for (int j = 0; j < 4; j++) {
        int idx = tid + j * 512;
        int r = idx >> 5, k = idx & 31;
        sx [k * PADX + r] = rx[j];
        swo[k * PADO + r] = rw[j].x;
        sws[k * PADO + r] = rw[j].y;
        sbs[k * PADO + r] = rb[j];
    }
    __syncthreads();

    const ull C3 = pk2(-1.6666667e-1f, -1.6666667e-1f);
    const ull C5 = pk2( 8.3333333e-3f,  8.3333333e-3f);

    ull acc[2][2];  // [bb][oo-pair]
    acc[0][0] = acc[0][1] = acc[1][0] = acc[1][1] = 0ull;

    for (int k0 = 0; k0 < IN_DIM; k0 += BK) {
        if (k0 + BK < IN_DIM) {
            #pragma unroll
            for (int j = 0; j < 4; j++) {
                int idx = tid + j * 512;
                int r = idx >> 5, k = idx & 31;
                rx[j] = x[(bRow + r) * IN_DIM + k0 + BK + k];
                rw[j] = w2[(oCol + r) * IN_DIM + k0 + BK + k];
                rb[j] = bias[(oCol + r) * (IN_DIM + 1) + k0 + BK + k];
            }
        }

        #pragma unroll 4
        for (int k = 0; k < BK; k++) {
            float2 xv = *(const float2*)&sx [k * PADX + ty * 2];
            float4 ws = *(const float4*)&sws[k * PADO + tx * 4];
            float4 bs = *(const float4*)&sbs[k * PADO + tx * 4];
            float4 wo = *(const float4*)&swo[k * PADO + tx * 4];

            ull wsp0 = pk2(ws.x, ws.y), wsp1 = pk2(ws.z, ws.w);
            ull bsp0 = pk2(bs.x, bs.y), bsp1 = pk2(bs.z, bs.w);
            ull wop0 = pk2(wo.x, wo.y), wop1 = pk2(wo.z, wo.w);

            float xb[2] = {xv.x, xv.y};
            #pragma unroll
            for (int bb = 0; bb < 2; bb++) {
                ull xd = pk2(xb[bb], xb[bb]);

                // oo pair 0 -> MUFU
                ull t0 = fma2_(xd, wsp0, bsp0);
                float l, h; upk2(t0, l, h);
                l = sin_mufu(l);
                h = sin_mufu(h);
                acc[bb][0] = fma2_(pk2(l, h), wop0, acc[bb][0]);

                // oo pair 1 -> poly: sin t = t + c3 t^3 + c5 t^5
                ull t1 = fma2_(xd, wsp1, bsp1);
                ull tt = mul2_(t1, t1);
                ull r  = fma2_(C5, tt, C3);
                r      = mul2_(r, tt);
                ull s  = fma2_(r, t1, t1);
                acc[bb][1] = fma2_(s, wop1, acc[bb][1]);
            }
        }

        __syncthreads();
        if (k0 + BK < IN_DIM) {
            #pragma unroll
            for (int j = 0; j < 4; j++) {
                int idx = tid + j * 512;
                int r = idx >> 5, k = idx & 31;
                sx [k * PADX + r] = rx[j];
                swo[k * PADO + r] = rw[j].x;
                sws[k * PADO + r] = rw[j].y;
                sbs[k * PADO + r] = rb[j];
            }
            __syncthreads();
        }
    }

    // ---- epilogue ----
    float bo[4];
    #pragma unroll
    for (int oo = 0; oo < 4; oo++)
        bo[oo] = bias[(oCol + tx * 4 + oo) * (IN_DIM + 1) + IN_DIM];

    #pragma unroll
    for (int bb = 0; bb < 2; bb++) {
        float a0, a1, a2, a3;
        upk2(acc[bb][0], a0, a1);
        upk2(acc[bb][1], a2, a3);
        float4 v;
        v.x = a0 + bo[0];
        v.y = a1 + bo[1];
        v.z = a2 + bo[2];
        v.w = a3 + bo[3];
        *(float4*)&out[(bRow + ty * 2 + bb) * OUT_DIM + oCol + tx * 4] = v;
    }
}

extern "C" void kernel_launch(void* const* d_in, const int* in_sizes, int n_in,
                              void* d_out, int out_size) {
    const float* x      = (const float*)d_in[0];
    const float* weight = (const float*)d_in[1];
    const float* bias   = (const float*)d_in[2];
    float* out          = (float*)d_out;

    dim3 grid(OUT_DIM / BN, B_DIM / BM);  // (8, 16) = 128 CTAs
    trigo_kernel<<<grid, 512>>>(x, weight, bias, out);
}

// round 5
// speedup vs baseline: 1.1504x; 1.1504x over previous
#include <cuda_runtime.h>

// TrigoLinear: out[b,o] = sum_i sin(x[b,i]*w_sin[o,i] + b_sin[o,i]) * w_out[o,i] + b_out[o]
// R2 inner loop (best measured mix) + k-split x2 for 4 warps/SMSP.
// Main kernel writes partials to static buffer; combine kernel adds them + b_out.

#define B_DIM   1024
#define IN_DIM  512
#define OUT_DIM 512

#define BM 64
#define BN 64
#define BK 32
#define KSPLIT 2
#define KHALF (IN_DIM / KSPLIT)   // 256
#define PAD 68

typedef unsigned long long ull;

__device__ float g_partial[KSPLIT][B_DIM * OUT_DIM];  // 4MB static scratch

__device__ __forceinline__ ull pk2(float lo, float hi) {
    ull d; asm("mov.b64 %0, {%1, %2};" : "=l"(d) : "f"(lo), "f"(hi)); return d;
}
__device__ __forceinline__ void upk2(ull d, float& lo, float& hi) {
    asm("mov.b64 {%0, %1}, %2;" : "=f"(lo), "=f"(hi) : "l"(d));
}
__device__ __forceinline__ ull fma2_(ull a, ull b, ull c) {
    ull d; asm("fma.rn.f32x2 %0, %1, %2, %3;" : "=l"(d) : "l"(a), "l"(b), "l"(c)); return d;
}
__device__ __forceinline__ ull mul2_(ull a, ull b) {
    ull d; asm("mul.rn.f32x2 %0, %1, %2;" : "=l"(d) : "l"(a), "l"(b)); return d;
}
__device__ __forceinline__ float sin_mufu(float a) {
    float d; asm("sin.approx.f32 %0, %1;" : "=f"(d) : "f"(a)); return d;
}

__global__ __launch_bounds__(256, 2)
void trigo_main(const float* __restrict__ x,
                const float* __restrict__ weight,
                const float* __restrict__ bias) {
    __shared__ __align__(16) float sx [BK * PAD];  // [k][b]
    __shared__ __align__(16) float sws[BK * PAD];  // [k][o] w_sin
    __shared__ __align__(16) float sbs[BK * PAD];  // [k][o] b_sin
    __shared__ __align__(16) float swo[BK * PAD];  // [k][o] w_out

    const int tid = threadIdx.x;
    const int tx = tid & 15;   // 4 outs/thread
    const int ty = tid >> 4;   // 4 rows/thread
    const int bRow = blockIdx.y * BM;
    const int oCol = blockIdx.x * BN;
    const int kBase = blockIdx.z * KHALF;

    const float2* __restrict__ w2 = (const float2*)weight;

    const ull C3 = pk2(-1.6666667e-1f, -1.6666667e-1f);
    const ull C5 = pk2( 8.3333333e-3f,  8.3333333e-3f);

    ull acc[4][2];
    #pragma unroll
    for (int bb = 0; bb < 4; bb++) { acc[bb][0] = 0ull; acc[bb][1] = 0ull; }

    for (int k0 = kBase; k0 < kBase + KHALF; k0 += BK) {
        // ---- stage tiles (no reg pipeline; latency hidden by 4 warps/SMSP) ----
        #pragma unroll
        for (int j = 0; j < 8; j++) {
            int idx = tid + j * 256;
            int r = idx >> 5, k = idx & 31;
            sx[k * PAD + r] = x[(bRow + r) * IN_DIM + k0 + k];
        }
        #pragma unroll
        for (int j = 0; j < 8; j++) {
            int idx = tid + j * 256;
            int r = idx >> 5, k = idx & 31;
            float2 w = w2[(oCol + r) * IN_DIM + k0 + k];
            swo[k * PAD + r] = w.x;
            sws[k * PAD + r] = w.y;
            sbs[k * PAD + r] = bias[(oCol + r) * (IN_DIM + 1) + k0 + k];
        }
        __syncthreads();

        #pragma unroll 4
        for (int k = 0; k < BK; k++) {
            float4 xb = *(const float4*)&sx [k * PAD + ty * 4];
            float4 ws = *(const float4*)&sws[k * PAD + tx * 4];
            float4 bs = *(const float4*)&sbs[k * PAD + tx * 4];
            float4 wo = *(const float4*)&swo[k * PAD + tx * 4];

            ull wsp0 = pk2(ws.x, ws.y), wsp1 = pk2(ws.z, ws.w);
            ull bsp0 = pk2(bs.x, bs.y), bsp1 = pk2(bs.z, bs.w);
            ull wop0 = pk2(wo.x, wo.y), wop1 = pk2(wo.z, wo.w);

            float xv[4] = {xb.x, xb.y, xb.z, xb.w};
            #pragma unroll
            for (int bb = 0; bb < 4; bb++) {
                ull xd = pk2(xv[bb], xv[bb]);

                // oo pair 0 -> MUFU pipe
                ull t0 = fma2_(xd, wsp0, bsp0);
                float l, h; upk2(t0, l, h);
                l = sin_mufu(l);
                h = sin_mufu(h);
                acc[bb][0] = fma2_(pk2(l, h), wop0, acc[bb][0]);

                // oo pair 1 -> FMA pipe, sin t = t + c3 t^3 + c5 t^5
                ull t1 = fma2_(xd, wsp1, bsp1);
                ull tt = mul2_(t1, t1);
                ull r  = fma2_(C5, tt, C3);
                r      = mul2_(r, tt);
                ull s  = fma2_(r, t1, t1);
                acc[bb][1] = fma2_(s, wop1, acc[bb][1]);
            }
        }
        __syncthreads();
    }

    // ---- write partials (exclusive per blockIdx.z) ----
    float* part = g_partial[blockIdx.z];
    #pragma unroll
    for (int bb = 0; bb < 4; bb++) {
        float a0, a1, a2, a3;
        upk2(acc[bb][0], a0, a1);
        upk2(acc[bb][1], a2, a3);
        float4 v = {a0, a1, a2, a3};
        *(float4*)&part[(bRow + ty * 4 + bb) * OUT_DIM + oCol + tx * 4] = v;
    }
}

__global__ __launch_bounds__(256, 4)
void trigo_combine(const float* __restrict__ bias,
                   float* __restrict__ out) {
    int idx = (blockIdx.x * 256 + threadIdx.x) * 4;   // element index, float4 granularity
    int o = idx & (OUT_DIM - 1);

    float4 p0 = *(const float4*)&g_partial[0][idx];
    float4 p1 = *(const float4*)&g_partial[1][idx];
    float4 v;
    v.x = p0.x + p1.x + bias[(o + 0) * (IN_DIM + 1) + IN_DIM];
    v.y = p0.y + p1.y + bias[(o + 1) * (IN_DIM + 1) + IN_DIM];
    v.z = p0.z + p1.z + bias[(o + 2) * (IN_DIM + 1) + IN_DIM];
    v.w = p0.w + p1.w + bias[(o + 3) * (IN_DIM + 1) + IN_DIM];
    *(float4*)&out[idx] = v;
}

extern "C" void kernel_launch(void* const* d_in, const int* in_sizes, int n_in,
                              void* d_out, int out_size) {
    const float* x      = (const float*)d_in[0];
    const float* weight = (const float*)d_in[1];
    const float* bias   = (const float*)d_in[2];
    float* out          = (float*)d_out;

    dim3 grid(OUT_DIM / BN, B_DIM / BM, KSPLIT);  // (8, 16, 2) = 256 CTAs
    trigo_main<<<grid, 256>>>(x, weight, bias);

    int nvec = B_DIM * OUT_DIM / 4;                // 131072 float4s
    trigo_combine<<<nvec / 256, 256>>>(bias, out);
}